// round 7
// baseline (speedup 1.0000x reference)
#include <cuda_runtime.h>
#include <cuda_bf16.h>
#include <mma.h>
#include <stdint.h>
#include <math.h>

using namespace nvcuda;

#define NMAX 50048   // 391 * 128, WMMA tile stores never OOB
#define EMAX 1000000

__device__ __nv_bfloat16 g_W[3][2][2][128*128]; // [layer][0=Wm,1=Wu][hi/lo][c][k]
__device__ float g_agg[NMAX*128];
__device__ float g_u[NMAX*128];
__device__ float g_h[2][NMAX*128];
__device__ int   g_is64;
__device__ int   g_cnt[NMAX];
__device__ int   g_off[NMAX + 1];
__device__ int   g_cur[NMAX];
__device__ int   g_src_sorted[EMAX];
__device__ float g_w_sorted[EMAX];

// ================= prep: weights -> bf16 hi/lo =================
__global__ void prep_kernel(const float* __restrict__ Wm0, const float* __restrict__ Wu0,
                            const float* __restrict__ Wm1, const float* __restrict__ Wu1,
                            const float* __restrict__ Wm2, const float* __restrict__ Wu2) {
    int idx = blockIdx.x * blockDim.x + threadIdx.x;
    const int total = 3 * 2 * 128 * 128;
    for (int t = idx; t < total; t += gridDim.x * blockDim.x) {
        int l = t / (2 * 128 * 128);
        int r = t % (2 * 128 * 128);
        int ty = r / (128 * 128);          // 0=Wm, 1=Wu
        int e  = r % (128 * 128);
        const float* W;
        if (ty == 0) W = (l == 0) ? Wm0 : (l == 1) ? Wm1 : Wm2;
        else         W = (l == 0) ? Wu0 : (l == 1) ? Wu1 : Wu2;
        float v = W[e];
        __nv_bfloat16 hi = __float2bfloat16(v);
        __nv_bfloat16 lo = __float2bfloat16(v - __bfloat162float(hi));
        g_W[l][ty][0][e] = hi;
        g_W[l][ty][1][e] = lo;
    }
}

// ================= CSR build (forked stream) =================
__global__ void zero_kernel(const void* __restrict__ ei, int N) {
    int idx = blockIdx.x * blockDim.x + threadIdx.x;
    if (idx == 0) {
        const int* p = (const int*)ei;
        int is64 = 1;
        for (int i = 0; i < 32; i++) if (p[2*i + 1] != 0) { is64 = 0; break; }
        g_is64 = is64;
    }
    for (int t = idx; t < N; t += gridDim.x * blockDim.x) g_cnt[t] = 0;
}

__global__ void hist_kernel(const void* __restrict__ ei, int E) {
    int i = blockIdx.x * blockDim.x + threadIdx.x;
    if (i >= E) return;
    int dst = g_is64 ? (int)((const long long*)ei)[E + i] : ((const int*)ei)[E + i];
    atomicAdd(&g_cnt[dst], 1);
}

__global__ __launch_bounds__(1024) void scan_kernel(int N) {
    __shared__ int part[1024];
    int t = threadIdx.x;
    int chunk = (N + 1023) / 1024;
    int b = t * chunk;
    int e = min(b + chunk, N);
    int s = 0;
    for (int i = b; i < e; i++) s += g_cnt[i];
    part[t] = s;
    __syncthreads();
    for (int d = 1; d < 1024; d <<= 1) {
        int v = (t >= d) ? part[t - d] : 0;
        __syncthreads();
        part[t] += v;
        __syncthreads();
    }
    int run = (t == 0) ? 0 : part[t - 1];
    for (int i = b; i < e; i++) {
        int c = g_cnt[i];
        g_off[i] = run;
        g_cur[i] = run;
        run += c;
    }
    if (e == N && b <= N) g_off[N] = run;
}

__global__ void scatter_kernel(const void* __restrict__ ei, const float* __restrict__ ew, int E) {
    int i = blockIdx.x * blockDim.x + threadIdx.x;
    if (i >= E) return;
    int src, dst;
    if (g_is64) {
        const long long* p = (const long long*)ei;
        src = (int)p[i]; dst = (int)p[E + i];
    } else {
        const int* p = (const int*)ei;
        src = p[i]; dst = p[E + i];
    }
    int pos = atomicAdd(&g_cur[dst], 1);
    g_src_sorted[pos] = src;
    g_w_sorted[pos]   = ew[i];
}

// ================= x-domain CSR aggregate: agg[d] = sum_e w_e * x[src_e] =================
__global__ __launch_bounds__(256) void agg_kernel(
    const float* __restrict__ x, float* __restrict__ agg, int N)
{
    int node = (blockIdx.x * blockDim.x + threadIdx.x) >> 5;
    int lane = threadIdx.x & 31;
    if (node >= N) return;
    int b = g_off[node], e = g_off[node + 1];

    float4 acc = make_float4(0.f, 0.f, 0.f, 0.f);

    int i = b;
    for (; i + 4 <= e; i += 4) {
        int   s0 = g_src_sorted[i],   s1 = g_src_sorted[i+1];
        int   s2 = g_src_sorted[i+2], s3 = g_src_sorted[i+3];
        float w0 = g_w_sorted[i],     w1 = g_w_sorted[i+1];
        float w2 = g_w_sorted[i+2],   w3 = g_w_sorted[i+3];
        float4 v0 = *(const float4*)(x + (size_t)s0*128 + lane*4);
        float4 v1 = *(const float4*)(x + (size_t)s1*128 + lane*4);
        float4 v2 = *(const float4*)(x + (size_t)s2*128 + lane*4);
        float4 v3 = *(const float4*)(x + (size_t)s3*128 + lane*4);
        acc.x = fmaf(w0, v0.x, fmaf(w1, v1.x, fmaf(w2, v2.x, fmaf(w3, v3.x, acc.x))));
        acc.y = fmaf(w0, v0.y, fmaf(w1, v1.y, fmaf(w2, v2.y, fmaf(w3, v3.y, acc.y))));
        acc.z = fmaf(w0, v0.z, fmaf(w1, v1.z, fmaf(w2, v2.z, fmaf(w3, v3.z, acc.z))));
        acc.w = fmaf(w0, v0.w, fmaf(w1, v1.w, fmaf(w2, v2.w, fmaf(w3, v3.w, acc.w))));
    }
    for (; i < e; i++) {
        int   s = g_src_sorted[i];
        float w = g_w_sorted[i];
        float4 v = *(const float4*)(x + (size_t)s*128 + lane*4);
        acc.x = fmaf(w, v.x, acc.x);
        acc.y = fmaf(w, v.y, acc.y);
        acc.z = fmaf(w, v.z, acc.z);
        acc.w = fmaf(w, v.w, acc.w);
    }
    *(float4*)(agg + (size_t)node*128 + lane*4) = acc;
}

// ================= shared staging helper =================
#define LDP 136
__device__ __forceinline__ void stage_hi_lo(const float* __restrict__ src, int row0, int N,
                                            __nv_bfloat16* dH, __nv_bfloat16* dL, int tid) {
    for (int ch = tid; ch < 2048; ch += 256) {
        int r  = ch >> 4;
        int c0 = (ch & 15) << 3;
        float v[8];
        int gr = row0 + r;
        if (gr < N) {
            float4 a = *(const float4*)(src + (size_t)gr * 128 + c0);
            float4 b = *(const float4*)(src + (size_t)gr * 128 + c0 + 4);
            v[0]=a.x; v[1]=a.y; v[2]=a.z; v[3]=a.w; v[4]=b.x; v[5]=b.y; v[6]=b.z; v[7]=b.w;
        } else {
            #pragma unroll
            for (int j = 0; j < 8; j++) v[j] = 0.f;
        }
        union { unsigned short u[8]; uint4 q; } H, L;
        #pragma unroll
        for (int j = 0; j < 8; j++) {
            __nv_bfloat16 hv = __float2bfloat16(v[j]);
            __nv_bfloat16 lv = __float2bfloat16(v[j] - __bfloat162float(hv));
            H.u[j] = __bfloat16_as_ushort(hv);
            L.u[j] = __bfloat16_as_ushort(lv);
        }
        *(uint4*)(dH + r * LDP + c0) = H.q;
        *(uint4*)(dL + r * LDP + c0) = L.q;
    }
}

// ================= u GEMM: u = x@Wu.T + bu =================
#define UG_XH 0
#define UG_XL (128*LDP*2)
#define UG_WH (2*128*LDP*2)
#define UG_WL (3*128*LDP*2)
#define UG_BS (4*128*LDP*2)
#define UG_SMEM (UG_BS + 16*LDP*4)

__global__ __launch_bounds__(256, 1) void u_gemm_wmma(
    const float* __restrict__ x,
    const __nv_bfloat16* __restrict__ Whi, const __nv_bfloat16* __restrict__ Wlo,
    const float* __restrict__ bu, float* __restrict__ outu, int N)
{
    extern __shared__ char sm[];
    __nv_bfloat16* xsH = (__nv_bfloat16*)(sm + UG_XH);
    __nv_bfloat16* xsL = (__nv_bfloat16*)(sm + UG_XL);
    __nv_bfloat16* wsH = (__nv_bfloat16*)(sm + UG_WH);
    __nv_bfloat16* wsL = (__nv_bfloat16*)(sm + UG_WL);
    float* bs = (float*)(sm + UG_BS);
    int tid = threadIdx.x, warp = tid >> 5;

    for (int i = tid; i < 128 * 16; i += 256) {
        int r = i >> 4, ch = i & 15;
        ((uint4*)(wsH + r * LDP))[ch] = ((const uint4*)(Whi + r * 128))[ch];
        ((uint4*)(wsL + r * LDP))[ch] = ((const uint4*)(Wlo + r * 128))[ch];
    }
    for (int i = tid; i < 16 * LDP; i += 256) {
        int c = i % LDP;
        bs[i] = (c < 128) ? bu[c] : 0.f;
    }

    int ntiles = (N + 127) >> 7;
    for (int tile = blockIdx.x; tile < ntiles; tile += gridDim.x) {
        int row0 = tile << 7;
        __syncthreads();
        stage_hi_lo(x, row0, N, xsH, xsL, tid);
        __syncthreads();

        wmma::fragment<wmma::accumulator, 16, 16, 16, float> acc[8];
        #pragma unroll
        for (int f = 0; f < 8; f++)
            wmma::load_matrix_sync(acc[f], bs + f * 16, LDP, wmma::mem_row_major);

        #pragma unroll
        for (int pass = 0; pass < 3; pass++) {
            const __nv_bfloat16* A = (pass == 2) ? xsL : xsH;
            const __nv_bfloat16* B = (pass == 1) ? wsL : wsH;
            #pragma unroll
            for (int k = 0; k < 8; k++) {
                wmma::fragment<wmma::matrix_a, 16, 16, 16, __nv_bfloat16, wmma::row_major> af;
                wmma::load_matrix_sync(af, A + (warp * 16) * LDP + k * 16, LDP);
                #pragma unroll
                for (int f = 0; f < 8; f++) {
                    wmma::fragment<wmma::matrix_b, 16, 16, 16, __nv_bfloat16, wmma::col_major> bf;
                    wmma::load_matrix_sync(bf, B + (f * 16) * LDP + k * 16, LDP);
                    wmma::mma_sync(acc[f], af, bf, acc[f]);
                }
            }
        }
        int gr0 = row0 + warp * 16;   // padded buffer, always in-bounds
        #pragma unroll
        for (int f = 0; f < 8; f++)
            wmma::store_matrix_sync(outu + (size_t)gr0 * 128 + f * 16, acc[f], 128, wmma::mem_row_major);
    }
}

// ================= m GEMM + tanh: h = tanh(agg@Wm.T + u) =================
#define MG_AH 0
#define MG_AL (128*LDP*2)
#define MG_WH (2*128*LDP*2)
#define MG_WL (3*128*LDP*2)
#define MG_EPI (4*128*LDP*2)
#define MG_SMEM (MG_EPI + 8*16*LDP*4)

__global__ __launch_bounds__(256, 1) void m_gemm_wmma(
    const float* __restrict__ agg,
    const __nv_bfloat16* __restrict__ Whi, const __nv_bfloat16* __restrict__ Wlo,
    const float* __restrict__ u, float* __restrict__ h, int N)
{
    extern __shared__ char sm[];
    __nv_bfloat16* asH = (__nv_bfloat16*)(sm + MG_AH);
    __nv_bfloat16* asL = (__nv_bfloat16*)(sm + MG_AL);
    __nv_bfloat16* wsH = (__nv_bfloat16*)(sm + MG_WH);
    __nv_bfloat16* wsL = (__nv_bfloat16*)(sm + MG_WL);
    int tid = threadIdx.x, warp = tid >> 5, lane = tid & 31;
    float* epi = (float*)(sm + MG_EPI) + warp * 16 * LDP;

    for (int i = tid; i < 128 * 16; i += 256) {
        int r = i >> 4, ch = i & 15;
        ((uint4*)(wsH + r * LDP))[ch] = ((const uint4*)(Whi + r * 128))[ch];
        ((uint4*)(wsL + r * LDP))[ch] = ((const uint4*)(Wlo + r * 128))[ch];
    }

    int ntiles = (N + 127) >> 7;
    for (int tile = blockIdx.x; tile < ntiles; tile += gridDim.x) {
        int row0 = tile << 7;
        __syncthreads();
        stage_hi_lo(agg, row0, N, asH, asL, tid);
        __syncthreads();

        int gr0 = row0 + warp * 16;
        wmma::fragment<wmma::accumulator, 16, 16, 16, float> acc[8];
        #pragma unroll
        for (int f = 0; f < 8; f++)
            wmma::load_matrix_sync(acc[f], u + (size_t)gr0 * 128 + f * 16, 128, wmma::mem_row_major);

        #pragma unroll
        for (int pass = 0; pass < 3; pass++) {
            const __nv_bfloat16* A = (pass == 2) ? asL : asH;
            const __nv_bfloat16* B = (pass == 1) ? wsL : wsH;
            #pragma unroll
            for (int k = 0; k < 8; k++) {
                wmma::fragment<wmma::matrix_a, 16, 16, 16, __nv_bfloat16, wmma::row_major> af;
                wmma::load_matrix_sync(af, A + (warp * 16) * LDP + k * 16, LDP);
                #pragma unroll
                for (int f = 0; f < 8; f++) {
                    wmma::fragment<wmma::matrix_b, 16, 16, 16, __nv_bfloat16, wmma::col_major> bf;
                    wmma::load_matrix_sync(bf, B + (f * 16) * LDP + k * 16, LDP);
                    wmma::mma_sync(acc[f], af, bf, acc[f]);
                }
            }
        }
        #pragma unroll
        for (int f = 0; f < 8; f++)
            wmma::store_matrix_sync(epi + f * 16, acc[f], LDP, wmma::mem_row_major);
        __syncwarp();
        #pragma unroll
        for (int r = 0; r < 16; r++) {
            float4 v = *(float4*)(epi + r * LDP + lane * 4);
            v.x = tanhf(v.x); v.y = tanhf(v.y); v.z = tanhf(v.z); v.w = tanhf(v.w);
            *(float4*)(h + (size_t)(gr0 + r) * 128 + lane * 4) = v;
        }
    }
}

// ================= WMMA output GEMM: out = h @ Wout.T + bout (C=32) =================
#define OLDP 136
#define OA_H 0
#define OA_L (128*OLDP*2)
#define OW_H (2*128*OLDP*2)
#define OW_L (OW_H + 32*OLDP*2)
#define OBIAS (OW_L + 32*OLDP*2)
#define OUT_SMEM (OBIAS + 16*40*4)

__global__ __launch_bounds__(256, 1) void out_gemm_wmma(
    const float* __restrict__ h, const float* __restrict__ Wout,
    const float* __restrict__ bout, float* __restrict__ out,
    float* __restrict__ scratch, int N)
{
    extern __shared__ char sm[];
    __nv_bfloat16* aH = (__nv_bfloat16*)(sm + OA_H);
    __nv_bfloat16* aL = (__nv_bfloat16*)(sm + OA_L);
    __nv_bfloat16* wH = (__nv_bfloat16*)(sm + OW_H);
    __nv_bfloat16* wL = (__nv_bfloat16*)(sm + OW_L);
    float* bs = (float*)(sm + OBIAS);
    int tid = threadIdx.x, warp = tid >> 5, lane = tid & 31;

    for (int i = tid; i < 32 * 16; i += 256) {
        int r = i >> 4, ch = i & 15;
        float4 a = *(const float4*)(Wout + r * 128 + ch * 8);
        float4 b = *(const float4*)(Wout + r * 128 + ch * 8 + 4);
        float v[8] = {a.x, a.y, a.z, a.w, b.x, b.y, b.z, b.w};
        union { unsigned short u[8]; uint4 q; } H, L;
        #pragma unroll
        for (int j = 0; j < 8; j++) {
            __nv_bfloat16 hv = __float2bfloat16(v[j]);
            __nv_bfloat16 lv = __float2bfloat16(v[j] - __bfloat162float(hv));
            H.u[j] = __bfloat16_as_ushort(hv);
            L.u[j] = __bfloat16_as_ushort(lv);
        }
        *(uint4*)(wH + r * OLDP + ch * 8) = H.q;
        *(uint4*)(wL + r * OLDP + ch * 8) = L.q;
    }
    for (int i = tid; i < 16 * 40; i += 256) {
        int c = i % 40;
        bs[i] = (c < 32) ? bout[c] : 0.f;
    }

    int ntiles = (N + 127) >> 7;
    for (int tile = blockIdx.x; tile < ntiles; tile += gridDim.x) {
        int row0 = tile << 7;
        __syncthreads();
        stage_hi_lo(h, row0, N, aH, aL, tid);
        __syncthreads();

        wmma::fragment<wmma::accumulator, 16, 16, 16, float> acc[2];
        #pragma unroll
        for (int f = 0; f < 2; f++)
            wmma::load_matrix_sync(acc[f], bs + f * 16, 40, wmma::mem_row_major);

        #pragma unroll
        for (int pass = 0; pass < 3; pass++) {
            const __nv_bfloat16* A = (pass == 2) ? aL : aH;
            const __nv_bfloat16* B = (pass == 1) ? wL : wH;
            #pragma unroll
            for (int k = 0; k < 8; k++) {
                wmma::fragment<wmma::matrix_a, 16, 16, 16, __nv_bfloat16, wmma::row_major> af;
                wmma::load_matrix_sync(af, A + (warp * 16) * OLDP + k * 16, OLDP);
                #pragma unroll
                for (int f = 0; f < 2; f++) {
                    wmma::fragment<wmma::matrix_b, 16, 16, 16, __nv_bfloat16, wmma::col_major> bf;
                    wmma::load_matrix_sync(bf, B + (f * 16) * OLDP + k * 16, OLDP);
                    wmma::mma_sync(acc[f], af, bf, acc[f]);
                }
            }
        }
        int gr0 = row0 + warp * 16;
        if (gr0 + 16 <= N) {
            wmma::store_matrix_sync(out + (size_t)gr0 * 32,      acc[0], 32, wmma::mem_row_major);
            wmma::store_matrix_sync(out + (size_t)gr0 * 32 + 16, acc[1], 32, wmma::mem_row_major);
        } else if (gr0 < N) {
            float* sc = scratch + (size_t)gr0 * 32;
            wmma::store_matrix_sync(sc,      acc[0], 32, wmma::mem_row_major);
            wmma::store_matrix_sync(sc + 16, acc[1], 32, wmma::mem_row_major);
            __syncwarp();
            for (int r = 0; r < 16; r++) {
                int gr = gr0 + r;
                if (gr < N) out[(size_t)gr * 32 + lane] = sc[r * 32 + lane];
            }
        }
    }
}

extern "C" void kernel_launch(void* const* d_in, const int* in_sizes, int n_in,
                              void* d_out, int out_size) {
    const float* x    = (const float*)d_in[0];
    const void*  ei   = d_in[1];
    const float* ew   = (const float*)d_in[2];
    const float* Wm0  = (const float*)d_in[3];
    const float* Wu0  = (const float*)d_in[4];
    const float* bu0  = (const float*)d_in[5];
    const float* Wm1  = (const float*)d_in[6];
    const float* Wu1  = (const float*)d_in[7];
    const float* bu1  = (const float*)d_in[8];
    const float* Wm2  = (const float*)d_in[9];
    const float* Wu2  = (const float*)d_in[10];
    const float* bu2  = (const float*)d_in[11];
    const float* Wout = (const float*)d_in[12];
    const float* bout = (const float*)d_in[13];
    float* out = (float*)d_out;

    int N = in_sizes[0] / 128;
    int E = in_sizes[2];

    __nv_bfloat16* pW;
    float *pagg, *pu, *ph;
    cudaGetSymbolAddress((void**)&pW,   g_W);
    cudaGetSymbolAddress((void**)&pagg, g_agg);
    cudaGetSymbolAddress((void**)&pu,   g_u);
    cudaGetSymbolAddress((void**)&ph,   g_h);

    static cudaStream_t s2 = nullptr;
    static cudaEvent_t evF = nullptr, evA[3], evH[2];
    if (!s2) {
        cudaStreamCreateWithFlags(&s2, cudaStreamNonBlocking);
        cudaEventCreateWithFlags(&evF, cudaEventDisableTiming);
        for (int i = 0; i < 3; i++) cudaEventCreateWithFlags(&evA[i], cudaEventDisableTiming);
        for (int i = 0; i < 2; i++) cudaEventCreateWithFlags(&evH[i], cudaEventDisableTiming);
    }

    static bool attrs_set = false;
    if (!attrs_set) {
        cudaFuncSetAttribute(u_gemm_wmma,  cudaFuncAttributeMaxDynamicSharedMemorySize, UG_SMEM);
        cudaFuncSetAttribute(m_gemm_wmma,  cudaFuncAttributeMaxDynamicSharedMemorySize, MG_SMEM);
        cudaFuncSetAttribute(out_gemm_wmma, cudaFuncAttributeMaxDynamicSharedMemorySize, OUT_SMEM);
        attrs_set = true;
    }

    int eb = (E + 255) / 256;
    int ab = (N * 32 + 255) / 256;

    // fork: CSR build + layer-0 aggregation on s2
    cudaEventRecord(evF, 0);
    cudaStreamWaitEvent(s2, evF, 0);
    zero_kernel<<<148, 256, 0, s2>>>(ei, N);
    hist_kernel<<<eb, 256, 0, s2>>>(ei, E);
    scan_kernel<<<1, 1024, 0, s2>>>(N);
    scatter_kernel<<<eb, 256, 0, s2>>>(ei, ew, E);
    agg_kernel<<<ab, 256, 0, s2>>>(x, pagg, N);
    cudaEventRecord(evA[0], s2);

    prep_kernel<<<148, 256>>>(Wm0, Wu0, Wm1, Wu1, Wm2, Wu2);

    const float* cur = x;
    for (int l = 0; l < 3; l++) {
        const float* bu = (l == 0) ? bu0 : (l == 1) ? bu1 : bu2;
        const __nv_bfloat16* Wm_hi = pW + ((size_t)l * 4 + 0) * 128 * 128;
        const __nv_bfloat16* Wm_lo = pW + ((size_t)l * 4 + 1) * 128 * 128;
        const __nv_bfloat16* Wu_hi = pW + ((size_t)l * 4 + 2) * 128 * 128;
        const __nv_bfloat16* Wu_lo = pW + ((size_t)l * 4 + 3) * 128 * 128;

        u_gemm_wmma<<<148, 256, UG_SMEM>>>(cur, Wu_hi, Wu_lo, bu, pu, N);
        cudaStreamWaitEvent(0, evA[l], 0);
        float* hbuf = ph + (size_t)(l & 1) * NMAX * 128;
        m_gemm_wmma<<<148, 256, MG_SMEM>>>(pagg, Wm_hi, Wm_lo, pu, hbuf, N);
        if (l < 2) {
            cudaEventRecord(evH[l], 0);
            cudaStreamWaitEvent(s2, evH[l], 0);
            agg_kernel<<<ab, 256, 0, s2>>>(hbuf, pagg, N);
            cudaEventRecord(evA[l + 1], s2);
        }
        cur = hbuf;
    }
    out_gemm_wmma<<<148, 256, OUT_SMEM>>>(cur, Wout, bout, out, pu, N);
    (void)n_in; (void)out_size;
}

// round 9
// speedup vs baseline: 1.1292x; 1.1292x over previous
#include <cuda_runtime.h>
#include <cuda_bf16.h>
#include <mma.h>
#include <stdint.h>
#include <math.h>

using namespace nvcuda;

#define NMAX 50048   // 391 * 128, WMMA tile stores never OOB
#define EMAX 1000000

__device__ __nv_bfloat16 g_Wbf[3][2][256*128]; // [layer][hi/lo][c][k], c<128 Wm, c>=128 Wu
__device__ float g_m[2][NMAX*128];   // double-buffered
__device__ float g_u[2][NMAX*128];   // double-buffered
__device__ float g_h[2][NMAX*128];
__device__ float g_scr[NMAX*32];
__device__ int   g_is64;
__device__ int   g_cnt[NMAX];
__device__ int   g_off[NMAX + 1];
__device__ int   g_cur[NMAX];
__device__ int   g_src_sorted[EMAX];
__device__ float g_w_sorted[EMAX];

// ================= prep: weights -> bf16 hi/lo =================
__global__ void prep_kernel(const float* __restrict__ Wm0, const float* __restrict__ Wu0,
                            const float* __restrict__ Wm1, const float* __restrict__ Wu1,
                            const float* __restrict__ Wm2, const float* __restrict__ Wu2) {
    int idx = blockIdx.x * blockDim.x + threadIdx.x;
    const int total = 3 * 256 * 128;
    for (int t = idx; t < total; t += gridDim.x * blockDim.x) {
        int l = t / (256 * 128);
        int r = t % (256 * 128);
        int c = r / 128;
        int k = r % 128;
        const float* W;
        if (c < 128) W = (l == 0) ? Wm0 : (l == 1) ? Wm1 : Wm2;
        else         W = (l == 0) ? Wu0 : (l == 1) ? Wu1 : Wu2;
        float v = W[(c & 127) * 128 + k];
        __nv_bfloat16 hi = __float2bfloat16(v);
        __nv_bfloat16 lo = __float2bfloat16(v - __bfloat162float(hi));
        g_Wbf[l][0][c * 128 + k] = hi;
        g_Wbf[l][1][c * 128 + k] = lo;
    }
}

// ================= CSR build (forked stream) =================
__global__ void zero_kernel(const void* __restrict__ ei, int N) {
    int idx = blockIdx.x * blockDim.x + threadIdx.x;
    if (idx == 0) {
        const int* p = (const int*)ei;
        int is64 = 1;
        for (int i = 0; i < 32; i++) if (p[2*i + 1] != 0) { is64 = 0; break; }
        g_is64 = is64;
    }
    for (int t = idx; t < N; t += gridDim.x * blockDim.x) g_cnt[t] = 0;
}

__global__ void hist_kernel(const void* __restrict__ ei, int E) {
    int i = blockIdx.x * blockDim.x + threadIdx.x;
    if (i >= E) return;
    int dst = g_is64 ? (int)((const long long*)ei)[E + i] : ((const int*)ei)[E + i];
    atomicAdd(&g_cnt[dst], 1);
}

__global__ __launch_bounds__(1024) void scan_kernel(int N) {
    __shared__ int part[1024];
    int t = threadIdx.x;
    int chunk = (N + 1023) / 1024;
    int b = t * chunk;
    int e = min(b + chunk, N);
    int s = 0;
    for (int i = b; i < e; i++) s += g_cnt[i];
    part[t] = s;
    __syncthreads();
    for (int d = 1; d < 1024; d <<= 1) {
        int v = (t >= d) ? part[t - d] : 0;
        __syncthreads();
        part[t] += v;
        __syncthreads();
    }
    int run = (t == 0) ? 0 : part[t - 1];
    for (int i = b; i < e; i++) {
        int c = g_cnt[i];
        g_off[i] = run;
        g_cur[i] = run;
        run += c;
    }
    if (e == N && b <= N) g_off[N] = run;
}

__global__ void scatter_kernel(const void* __restrict__ ei, const float* __restrict__ ew, int E) {
    int i = blockIdx.x * blockDim.x + threadIdx.x;
    if (i >= E) return;
    int src, dst;
    if (g_is64) {
        const long long* p = (const long long*)ei;
        src = (int)p[i]; dst = (int)p[E + i];
    } else {
        const int* p = (const int*)ei;
        src = p[i]; dst = p[E + i];
    }
    int pos = atomicAdd(&g_cur[dst], 1);
    g_src_sorted[pos] = src;
    g_w_sorted[pos]   = ew[i];
}

// ================= WMMA dual GEMM over row range [rb, re) =================
#define LDP 136
#define XS_H 0
#define XS_L (128*LDP*2)
#define WS_H (2*128*LDP*2)
#define WS_L (WS_H + 256*LDP*2)
#define GEMM_SMEM (WS_L + 256*LDP*2)

__global__ __launch_bounds__(256, 1) void dual_gemm_wmma(
    const float* __restrict__ x,
    const __nv_bfloat16* __restrict__ Whi, const __nv_bfloat16* __restrict__ Wlo,
    float* __restrict__ outm, float* __restrict__ outu, int rb, int re, int N)
{
    extern __shared__ char sm[];
    __nv_bfloat16* xsH = (__nv_bfloat16*)(sm + XS_H);
    __nv_bfloat16* xsL = (__nv_bfloat16*)(sm + XS_L);
    __nv_bfloat16* wsH = (__nv_bfloat16*)(sm + WS_H);
    __nv_bfloat16* wsL = (__nv_bfloat16*)(sm + WS_L);
    int tid = threadIdx.x, warp = tid >> 5;

    for (int i = tid; i < 256 * 16; i += 256) {
        int r = i >> 4, ch = i & 15;
        ((uint4*)(wsH + r * LDP))[ch] = ((const uint4*)(Whi + r * 128))[ch];
        ((uint4*)(wsL + r * LDP))[ch] = ((const uint4*)(Wlo + r * 128))[ch];
    }

    int t0 = rb >> 7;
    int t1 = (re + 127) >> 7;

    for (int tile = t0 + blockIdx.x; tile < t1; tile += gridDim.x) {
        int row0 = tile << 7;
        __syncthreads();
        for (int ch = tid; ch < 2048; ch += 256) {
            int r  = ch >> 4;
            int c0 = (ch & 15) << 3;
            float v[8];
            int gr = row0 + r;
            if (gr < N) {
                float4 a = *(const float4*)(x + (size_t)gr * 128 + c0);
                float4 b = *(const float4*)(x + (size_t)gr * 128 + c0 + 4);
                v[0]=a.x; v[1]=a.y; v[2]=a.z; v[3]=a.w; v[4]=b.x; v[5]=b.y; v[6]=b.z; v[7]=b.w;
            } else {
                #pragma unroll
                for (int j = 0; j < 8; j++) v[j] = 0.f;
            }
            union { unsigned short u[8]; uint4 q; } H, L;
            #pragma unroll
            for (int j = 0; j < 8; j++) {
                __nv_bfloat16 hv = __float2bfloat16(v[j]);
                __nv_bfloat16 lv = __float2bfloat16(v[j] - __bfloat162float(hv));
                H.u[j] = __bfloat16_as_ushort(hv);
                L.u[j] = __bfloat16_as_ushort(lv);
            }
            *(uint4*)(xsH + r * LDP + c0) = H.q;
            *(uint4*)(xsL + r * LDP + c0) = L.q;
        }
        __syncthreads();

        #pragma unroll
        for (int nc = 0; nc < 4; nc++) {
            wmma::fragment<wmma::accumulator, 16, 16, 16, float> acc[4];
            #pragma unroll
            for (int f = 0; f < 4; f++) wmma::fill_fragment(acc[f], 0.0f);

            #pragma unroll
            for (int pass = 0; pass < 3; pass++) {
                const __nv_bfloat16* A = (pass == 2) ? xsL : xsH;
                const __nv_bfloat16* B = (pass == 1) ? wsL : wsH;
                #pragma unroll
                for (int k = 0; k < 8; k++) {
                    wmma::fragment<wmma::matrix_a, 16, 16, 16, __nv_bfloat16, wmma::row_major> af;
                    wmma::load_matrix_sync(af, A + (warp * 16) * LDP + k * 16, LDP);
                    #pragma unroll
                    for (int f = 0; f < 4; f++) {
                        wmma::fragment<wmma::matrix_b, 16, 16, 16, __nv_bfloat16, wmma::col_major> bf;
                        wmma::load_matrix_sync(bf, B + (nc * 64 + f * 16) * LDP + k * 16, LDP);
                        wmma::mma_sync(acc[f], af, bf, acc[f]);
                    }
                }
            }
            int gr0 = row0 + warp * 16;   // padded buffers, never OOB
            #pragma unroll
            for (int f = 0; f < 4; f++) {
                int n0 = nc * 64 + f * 16;
                float* dst = (n0 < 128) ? (outm + (size_t)gr0 * 128 + n0)
                                        : (outu + (size_t)gr0 * 128 + (n0 - 128));
                wmma::store_matrix_sync(dst, acc[f], 128, wmma::mem_row_major);
            }
        }
    }
}

// ================= fused CSR aggregate + bias + tanh over node range =================
__global__ __launch_bounds__(256) void agg_tanh(
    const float* __restrict__ m, const float* __restrict__ u,
    const float* __restrict__ bu, float* __restrict__ h, int nb, int ne)
{
    int node = nb + ((blockIdx.x * blockDim.x + threadIdx.x) >> 5);
    int lane = threadIdx.x & 31;
    if (node >= ne) return;
    int b = g_off[node], e = g_off[node + 1];

    float4 bb = *(const float4*)(bu + lane*4);
    float4 uu = *(const float4*)(u + (size_t)node*128 + lane*4);
    float4 acc = make_float4(uu.x + bb.x, uu.y + bb.y, uu.z + bb.z, uu.w + bb.w);

    int i = b;
    for (; i + 4 <= e; i += 4) {
        int   s0 = g_src_sorted[i],   s1 = g_src_sorted[i+1];
        int   s2 = g_src_sorted[i+2], s3 = g_src_sorted[i+3];
        float w0 = g_w_sorted[i],     w1 = g_w_sorted[i+1];
        float w2 = g_w_sorted[i+2],   w3 = g_w_sorted[i+3];
        float4 v0 = *(const float4*)(m + (size_t)s0*128 + lane*4);
        float4 v1 = *(const float4*)(m + (size_t)s1*128 + lane*4);
        float4 v2 = *(const float4*)(m + (size_t)s2*128 + lane*4);
        float4 v3 = *(const float4*)(m + (size_t)s3*128 + lane*4);
        acc.x = fmaf(w0, v0.x, fmaf(w1, v1.x, fmaf(w2, v2.x, fmaf(w3, v3.x, acc.x))));
        acc.y = fmaf(w0, v0.y, fmaf(w1, v1.y, fmaf(w2, v2.y, fmaf(w3, v3.y, acc.y))));
        acc.z = fmaf(w0, v0.z, fmaf(w1, v1.z, fmaf(w2, v2.z, fmaf(w3, v3.z, acc.z))));
        acc.w = fmaf(w0, v0.w, fmaf(w1, v1.w, fmaf(w2, v2.w, fmaf(w3, v3.w, acc.w))));
    }
    for (; i < e; i++) {
        int   s = g_src_sorted[i];
        float w = g_w_sorted[i];
        float4 v = *(const float4*)(m + (size_t)s*128 + lane*4);
        acc.x = fmaf(w, v.x, acc.x);
        acc.y = fmaf(w, v.y, acc.y);
        acc.z = fmaf(w, v.z, acc.z);
        acc.w = fmaf(w, v.w, acc.w);
    }
    acc.x = tanhf(acc.x); acc.y = tanhf(acc.y);
    acc.z = tanhf(acc.z); acc.w = tanhf(acc.w);
    *(float4*)(h + (size_t)node*128 + lane*4) = acc;
}

// ================= WMMA output GEMM over row range =================
#define OLDP 136
#define OA_H 0
#define OA_L (128*OLDP*2)
#define OW_H (2*128*OLDP*2)
#define OW_L (OW_H + 32*OLDP*2)
#define OBIAS (OW_L + 32*OLDP*2)
#define OUT_SMEM (OBIAS + 16*40*4)

__global__ __launch_bounds__(256, 1) void out_gemm_wmma(
    const float* __restrict__ h, const float* __restrict__ Wout,
    const float* __restrict__ bout, float* __restrict__ out,
    float* __restrict__ scratch, int rb, int re, int N)
{
    extern __shared__ char sm[];
    __nv_bfloat16* aH = (__nv_bfloat16*)(sm + OA_H);
    __nv_bfloat16* aL = (__nv_bfloat16*)(sm + OA_L);
    __nv_bfloat16* wH = (__nv_bfloat16*)(sm + OW_H);
    __nv_bfloat16* wL = (__nv_bfloat16*)(sm + OW_L);
    float* bs = (float*)(sm + OBIAS);
    int tid = threadIdx.x, warp = tid >> 5, lane = tid & 31;

    for (int i = tid; i < 32 * 16; i += 256) {
        int r = i >> 4, ch = i & 15;
        float4 a = *(const float4*)(Wout + r * 128 + ch * 8);
        float4 b = *(const float4*)(Wout + r * 128 + ch * 8 + 4);
        float v[8] = {a.x, a.y, a.z, a.w, b.x, b.y, b.z, b.w};
        union { unsigned short u[8]; uint4 q; } H, L;
        #pragma unroll
        for (int j = 0; j < 8; j++) {
            __nv_bfloat16 hv = __float2bfloat16(v[j]);
            __nv_bfloat16 lv = __float2bfloat16(v[j] - __bfloat162float(hv));
            H.u[j] = __bfloat16_as_ushort(hv);
            L.u[j] = __bfloat16_as_ushort(lv);
        }
        *(uint4*)(wH + r * OLDP + ch * 8) = H.q;
        *(uint4*)(wL + r * OLDP + ch * 8) = L.q;
    }
    for (int i = tid; i < 16 * 40; i += 256) {
        int c = i % 40;
        bs[i] = (c < 32) ? bout[c] : 0.f;
    }

    int t0 = rb >> 7;
    int t1 = (re + 127) >> 7;
    for (int tile = t0 + blockIdx.x; tile < t1; tile += gridDim.x) {
        int row0 = tile << 7;
        __syncthreads();
        for (int ch = tid; ch < 2048; ch += 256) {
            int r  = ch >> 4;
            int c0 = (ch & 15) << 3;
            float v[8];
            int gr = row0 + r;
            if (gr < N) {
                float4 a = *(const float4*)(h + (size_t)gr * 128 + c0);
                float4 b = *(const float4*)(h + (size_t)gr * 128 + c0 + 4);
                v[0]=a.x; v[1]=a.y; v[2]=a.z; v[3]=a.w; v[4]=b.x; v[5]=b.y; v[6]=b.z; v[7]=b.w;
            } else {
                #pragma unroll
                for (int j = 0; j < 8; j++) v[j] = 0.f;
            }
            union { unsigned short u[8]; uint4 q; } H, L;
            #pragma unroll
            for (int j = 0; j < 8; j++) {
                __nv_bfloat16 hv = __float2bfloat16(v[j]);
                __nv_bfloat16 lv = __float2bfloat16(v[j] - __bfloat162float(hv));
                H.u[j] = __bfloat16_as_ushort(hv);
                L.u[j] = __bfloat16_as_ushort(lv);
            }
            *(uint4*)(aH + r * OLDP + c0) = H.q;
            *(uint4*)(aL + r * OLDP + c0) = L.q;
        }
        __syncthreads();

        wmma::fragment<wmma::accumulator, 16, 16, 16, float> acc[2];
        #pragma unroll
        for (int f = 0; f < 2; f++)
            wmma::load_matrix_sync(acc[f], bs + f * 16, 40, wmma::mem_row_major);

        #pragma unroll
        for (int pass = 0; pass < 3; pass++) {
            const __nv_bfloat16* A = (pass == 2) ? aL : aH;
            const __nv_bfloat16* B = (pass == 1) ? wL : wH;
            #pragma unroll
            for (int k = 0; k < 8; k++) {
                wmma::fragment<wmma::matrix_a, 16, 16, 16, __nv_bfloat16, wmma::row_major> af;
                wmma::load_matrix_sync(af, A + (warp * 16) * OLDP + k * 16, OLDP);
                #pragma unroll
                for (int f = 0; f < 2; f++) {
                    wmma::fragment<wmma::matrix_b, 16, 16, 16, __nv_bfloat16, wmma::col_major> bf;
                    wmma::load_matrix_sync(bf, B + (f * 16) * OLDP + k * 16, OLDP);
                    wmma::mma_sync(acc[f], af, bf, acc[f]);
                }
            }
        }
        int gr0 = row0 + warp * 16;
        if (gr0 + 16 <= N) {
            wmma::store_matrix_sync(out + (size_t)gr0 * 32,      acc[0], 32, wmma::mem_row_major);
            wmma::store_matrix_sync(out + (size_t)gr0 * 32 + 16, acc[1], 32, wmma::mem_row_major);
        } else if (gr0 < N) {
            float* sc = scratch + (size_t)gr0 * 32;
            wmma::store_matrix_sync(sc,      acc[0], 32, wmma::mem_row_major);
            wmma::store_matrix_sync(sc + 16, acc[1], 32, wmma::mem_row_major);
            __syncwarp();
            for (int r = 0; r < 16; r++) {
                int gr = gr0 + r;
                if (gr < N) out[(size_t)gr * 32 + lane] = sc[r * 32 + lane];
            }
        }
    }
}

extern "C" void kernel_launch(void* const* d_in, const int* in_sizes, int n_in,
                              void* d_out, int out_size) {
    const float* x    = (const float*)d_in[0];
    const void*  ei   = d_in[1];
    const float* ew   = (const float*)d_in[2];
    const float* Wm0  = (const float*)d_in[3];
    const float* Wu0  = (const float*)d_in[4];
    const float* bu0  = (const float*)d_in[5];
    const float* Wm1  = (const float*)d_in[6];
    const float* Wu1  = (const float*)d_in[7];
    const float* bu1  = (const float*)d_in[8];
    const float* Wm2  = (const float*)d_in[9];
    const float* Wu2  = (const float*)d_in[10];
    const float* bu2  = (const float*)d_in[11];
    const float* Wout = (const float*)d_in[12];
    const float* bout = (const float*)d_in[13];
    float* out = (float*)d_out;

    int N = in_sizes[0] / 128;
    int E = in_sizes[2];
    int Nh = (((N + 1) / 2) + 127) & ~127;    // half boundary, 128-aligned
    if (Nh > N) Nh = N;

    __nv_bfloat16* pW;
    float *pm, *pu, *ph, *psc;
    cudaGetSymbolAddress((void**)&pW,  g_Wbf);
    cudaGetSymbolAddress((void**)&pm,  g_m);
    cudaGetSymbolAddress((void**)&pu,  g_u);
    cudaGetSymbolAddress((void**)&ph,  g_h);
    cudaGetSymbolAddress((void**)&psc, g_scr);

    static cudaStream_t s2 = nullptr;
    static cudaEvent_t evF = nullptr, evCSR = nullptr, evA[3], evG[3];
    if (!s2) {
        cudaStreamCreateWithFlags(&s2, cudaStreamNonBlocking);
        cudaEventCreateWithFlags(&evF,   cudaEventDisableTiming);
        cudaEventCreateWithFlags(&evCSR, cudaEventDisableTiming);
        for (int i = 0; i < 3; i++) cudaEventCreateWithFlags(&evA[i], cudaEventDisableTiming);
        for (int i = 0; i < 3; i++) cudaEventCreateWithFlags(&evG[i], cudaEventDisableTiming);
    }

    static bool attrs_set = false;
    if (!attrs_set) {
        cudaFuncSetAttribute(dual_gemm_wmma, cudaFuncAttributeMaxDynamicSharedMemorySize, GEMM_SMEM);
        cudaFuncSetAttribute(out_gemm_wmma,  cudaFuncAttributeMaxDynamicSharedMemorySize, OUT_SMEM);
        attrs_set = true;
    }

    int eb = (E + 255) / 256;
    int abA = (Nh * 32 + 255) / 256;
    int abB = ((N - Nh) * 32 + 255) / 256;
    if (abB < 1) abB = 1;

    // fork: CSR build on s2
    cudaEventRecord(evF, 0);
    cudaStreamWaitEvent(s2, evF, 0);
    zero_kernel<<<148, 256, 0, s2>>>(ei, N);
    hist_kernel<<<eb, 256, 0, s2>>>(ei, E);
    scan_kernel<<<1, 1024, 0, s2>>>(N);
    scatter_kernel<<<eb, 256, 0, s2>>>(ei, ew, E);
    cudaEventRecord(evCSR, s2);

    // main: prep + full gemm0 -> buffers parity 0
    prep_kernel<<<148, 256>>>(Wm0, Wu0, Wm1, Wu1, Wm2, Wu2);
    dual_gemm_wmma<<<148, 256, GEMM_SMEM>>>(x, pW, pW + 256*128, pm, pu, 0, N, N);
    cudaStreamWaitEvent(0, evCSR, 0);

    const float* bus[3] = {bu0, bu1, bu2};
    for (int l = 0; l < 3; l++) {
        int p = l & 1;
        float* mp = pm + (size_t)p * NMAX * 128;        // read buffer this layer
        float* up = pu + (size_t)p * NMAX * 128;
        float* mn = pm + (size_t)(1 - p) * NMAX * 128;  // write buffer next layer
        float* un = pu + (size_t)(1 - p) * NMAX * 128;
        float* hbuf = ph + (size_t)p * NMAX * 128;

        // agg_A on main: read m[p]/u[p], write h[p] rows [0,Nh)
        agg_tanh<<<abA, 256>>>(mp, up, bus[l], hbuf, 0, Nh);
        cudaEventRecord(evA[l], 0);
        // s2: first half of next stage (writes OTHER parity buffers or out)
        cudaStreamWaitEvent(s2, evA[l], 0);
        if (l < 2) {
            const __nv_bfloat16* Whi = pW + (size_t)(l+1) * 2 * 256 * 128;
            const __nv_bfloat16* Wlo = Whi + 256 * 128;
            dual_gemm_wmma<<<148, 256, GEMM_SMEM, s2>>>(hbuf, Whi, Wlo, mn, un, 0, Nh, N);
        } else {
            out_gemm_wmma<<<148, 256, OUT_SMEM, s2>>>(hbuf, Wout, bout, out, psc, 0, Nh, N);
        }
        cudaEventRecord(evG[l], s2);
        // agg_B on main (concurrent with s2): still reads m[p]/u[p] only
        agg_tanh<<<abB, 256>>>(mp, up, bus[l], hbuf, Nh, N);
        // second half of next stage on main
        if (l < 2) {
            const __nv_bfloat16* Whi = pW + (size_t)(l+1) * 2 * 256 * 128;
            const __nv_bfloat16* Wlo = Whi + 256 * 128;
            dual_gemm_wmma<<<148, 256, GEMM_SMEM>>>(hbuf, Whi, Wlo, mn, un, Nh, N, N);
        } else {
            out_gemm_wmma<<<148, 256, OUT_SMEM>>>(hbuf, Wout, bout, out, psc, Nh, N, N);
        }
        cudaStreamWaitEvent(0, evG[l], 0);   // join s2 half before next layer consumes m[1-p]/u[1-p]
    }
    (void)n_in; (void)out_size;
}

// round 10
// speedup vs baseline: 1.3394x; 1.1862x over previous
#include <cuda_runtime.h>
#include <cuda_bf16.h>
#include <cuda_fp16.h>
#include <mma.h>
#include <stdint.h>
#include <math.h>

using namespace nvcuda;

#define NMAX 50048   // 391 * 128, WMMA tile stores never OOB
#define EMAX 1000000

__device__ __nv_bfloat16 g_Wbf[3][2][256*128]; // [layer][hi/lo][c][k], c<128 Wm, c>=128 Wu
__device__ __half g_m[NMAX*128];               // fp16 messages (halved gather traffic)
__device__ float  g_u[NMAX*128];
__device__ float  g_h[2][NMAX*128];
__device__ float  g_scr[NMAX*32];
__device__ int    g_is64;
__device__ int    g_cnt[NMAX];
__device__ int    g_off[NMAX + 1];
__device__ int    g_cur[NMAX];
__device__ int    g_src_sorted[EMAX];
__device__ float  g_w_sorted[EMAX];

// ================= prep: weights -> bf16 hi/lo =================
__global__ void prep_kernel(const float* __restrict__ Wm0, const float* __restrict__ Wu0,
                            const float* __restrict__ Wm1, const float* __restrict__ Wu1,
                            const float* __restrict__ Wm2, const float* __restrict__ Wu2) {
    int idx = blockIdx.x * blockDim.x + threadIdx.x;
    const int total = 3 * 256 * 128;
    for (int t = idx; t < total; t += gridDim.x * blockDim.x) {
        int l = t / (256 * 128);
        int r = t % (256 * 128);
        int c = r / 128;
        int k = r % 128;
        const float* W;
        if (c < 128) W = (l == 0) ? Wm0 : (l == 1) ? Wm1 : Wm2;
        else         W = (l == 0) ? Wu0 : (l == 1) ? Wu1 : Wu2;
        float v = W[(c & 127) * 128 + k];
        __nv_bfloat16 hi = __float2bfloat16(v);
        __nv_bfloat16 lo = __float2bfloat16(v - __bfloat162float(hi));
        g_Wbf[l][0][c * 128 + k] = hi;
        g_Wbf[l][1][c * 128 + k] = lo;
    }
}

// ================= CSR build (forked stream) =================
__global__ void zero_kernel(const void* __restrict__ ei, int N) {
    int idx = blockIdx.x * blockDim.x + threadIdx.x;
    if (idx == 0) {
        const int* p = (const int*)ei;
        int is64 = 1;
        for (int i = 0; i < 32; i++) if (p[2*i + 1] != 0) { is64 = 0; break; }
        g_is64 = is64;
    }
    for (int t = idx; t < N; t += gridDim.x * blockDim.x) g_cnt[t] = 0;
}

__global__ void hist_kernel(const void* __restrict__ ei, int E) {
    int i = blockIdx.x * blockDim.x + threadIdx.x;
    if (i >= E) return;
    int dst = g_is64 ? (int)((const long long*)ei)[E + i] : ((const int*)ei)[E + i];
    atomicAdd(&g_cnt[dst], 1);
}

__global__ __launch_bounds__(1024) void scan_kernel(int N) {
    __shared__ int part[1024];
    int t = threadIdx.x;
    int chunk = (N + 1023) / 1024;
    int b = t * chunk;
    int e = min(b + chunk, N);
    int s = 0;
    for (int i = b; i < e; i++) s += g_cnt[i];
    part[t] = s;
    __syncthreads();
    for (int d = 1; d < 1024; d <<= 1) {
        int v = (t >= d) ? part[t - d] : 0;
        __syncthreads();
        part[t] += v;
        __syncthreads();
    }
    int run = (t == 0) ? 0 : part[t - 1];
    for (int i = b; i < e; i++) {
        int c = g_cnt[i];
        g_off[i] = run;
        g_cur[i] = run;
        run += c;
    }
    if (e == N && b <= N) g_off[N] = run;
}

__global__ void scatter_kernel(const void* __restrict__ ei, const float* __restrict__ ew, int E) {
    int i = blockIdx.x * blockDim.x + threadIdx.x;
    if (i >= E) return;
    int src, dst;
    if (g_is64) {
        const long long* p = (const long long*)ei;
        src = (int)p[i]; dst = (int)p[E + i];
    } else {
        const int* p = (const int*)ei;
        src = p[i]; dst = p[E + i];
    }
    int pos = atomicAdd(&g_cur[dst], 1);
    g_src_sorted[pos] = src;
    g_w_sorted[pos]   = ew[i];
}

// ================= WMMA dual GEMM: m(fp16) = x@Wm.T ; u(fp32) = x@Wu.T =================
#define LDP 136
#define XS_H 0
#define XS_L (128*LDP*2)
#define WS_H (2*128*LDP*2)
#define WS_L (WS_H + 256*LDP*2)
#define G_EPI (WS_L + 256*LDP*2)
#define GEMM_SMEM (G_EPI + 8*256*4)

__global__ __launch_bounds__(256, 1) void dual_gemm_wmma(
    const float* __restrict__ x,
    const __nv_bfloat16* __restrict__ Whi, const __nv_bfloat16* __restrict__ Wlo,
    __half* __restrict__ outm, float* __restrict__ outu, int N)
{
    extern __shared__ char sm[];
    __nv_bfloat16* xsH = (__nv_bfloat16*)(sm + XS_H);
    __nv_bfloat16* xsL = (__nv_bfloat16*)(sm + XS_L);
    __nv_bfloat16* wsH = (__nv_bfloat16*)(sm + WS_H);
    __nv_bfloat16* wsL = (__nv_bfloat16*)(sm + WS_L);
    int tid = threadIdx.x, warp = tid >> 5, lane = tid & 31;
    float* ep = (float*)(sm + G_EPI) + warp * 256;   // per-warp 16x16 staging

    for (int i = tid; i < 256 * 16; i += 256) {
        int r = i >> 4, ch = i & 15;
        ((uint4*)(wsH + r * LDP))[ch] = ((const uint4*)(Whi + r * 128))[ch];
        ((uint4*)(wsL + r * LDP))[ch] = ((const uint4*)(Wlo + r * 128))[ch];
    }

    int ntiles = (N + 127) >> 7;

    for (int tile = blockIdx.x; tile < ntiles; tile += gridDim.x) {
        int row0 = tile << 7;
        __syncthreads();
        for (int ch = tid; ch < 2048; ch += 256) {
            int r  = ch >> 4;
            int c0 = (ch & 15) << 3;
            float v[8];
            int gr = row0 + r;
            if (gr < N) {
                float4 a = *(const float4*)(x + (size_t)gr * 128 + c0);
                float4 b = *(const float4*)(x + (size_t)gr * 128 + c0 + 4);
                v[0]=a.x; v[1]=a.y; v[2]=a.z; v[3]=a.w; v[4]=b.x; v[5]=b.y; v[6]=b.z; v[7]=b.w;
            } else {
                #pragma unroll
                for (int j = 0; j < 8; j++) v[j] = 0.f;
            }
            union { unsigned short u[8]; uint4 q; } H, L;
            #pragma unroll
            for (int j = 0; j < 8; j++) {
                __nv_bfloat16 hv = __float2bfloat16(v[j]);
                __nv_bfloat16 lv = __float2bfloat16(v[j] - __bfloat162float(hv));
                H.u[j] = __bfloat16_as_ushort(hv);
                L.u[j] = __bfloat16_as_ushort(lv);
            }
            *(uint4*)(xsH + r * LDP + c0) = H.q;
            *(uint4*)(xsL + r * LDP + c0) = L.q;
        }
        __syncthreads();

        int gr0 = row0 + warp * 16;   // padded buffers, never OOB
        #pragma unroll
        for (int nc = 0; nc < 4; nc++) {
            wmma::fragment<wmma::accumulator, 16, 16, 16, float> acc[4];
            #pragma unroll
            for (int f = 0; f < 4; f++) wmma::fill_fragment(acc[f], 0.0f);

            #pragma unroll
            for (int pass = 0; pass < 3; pass++) {
                const __nv_bfloat16* A = (pass == 2) ? xsL : xsH;
                const __nv_bfloat16* B = (pass == 1) ? wsL : wsH;
                #pragma unroll
                for (int k = 0; k < 8; k++) {
                    wmma::fragment<wmma::matrix_a, 16, 16, 16, __nv_bfloat16, wmma::row_major> af;
                    wmma::load_matrix_sync(af, A + (warp * 16) * LDP + k * 16, LDP);
                    #pragma unroll
                    for (int f = 0; f < 4; f++) {
                        wmma::fragment<wmma::matrix_b, 16, 16, 16, __nv_bfloat16, wmma::col_major> bf;
                        wmma::load_matrix_sync(bf, B + (nc * 64 + f * 16) * LDP + k * 16, LDP);
                        wmma::mma_sync(acc[f], af, bf, acc[f]);
                    }
                }
            }
            #pragma unroll
            for (int f = 0; f < 4; f++) {
                int n0 = nc * 64 + f * 16;
                if (n0 < 128) {
                    // fp16 m: stage fp32 fragment in smem, convert, vector-store
                    wmma::store_matrix_sync(ep, acc[f], 16, wmma::mem_row_major);
                    __syncwarp();
                    int row = lane >> 1, c0 = (lane & 1) * 8;
                    const float* s = ep + row * 16 + c0;
                    union { __half h[8]; uint4 q; } o;
                    #pragma unroll
                    for (int j = 0; j < 8; j++) o.h[j] = __float2half_rn(s[j]);
                    *(uint4*)(outm + (size_t)(gr0 + row) * 128 + n0 + c0) = o.q;
                    __syncwarp();
                } else {
                    wmma::store_matrix_sync(outu + (size_t)gr0 * 128 + (n0 - 128),
                                            acc[f], 128, wmma::mem_row_major);
                }
            }
        }
    }
}

// ================= fused CSR aggregate (fp16 gather) + bias + tanh =================
__global__ __launch_bounds__(256) void agg_tanh(
    const __half* __restrict__ m, const float* __restrict__ u,
    const float* __restrict__ bu, float* __restrict__ h, int N)
{
    int node = (blockIdx.x * blockDim.x + threadIdx.x) >> 5;
    int lane = threadIdx.x & 31;
    if (node >= N) return;
    int b = g_off[node], e = g_off[node + 1];

    float4 bb = *(const float4*)(bu + lane*4);
    float4 uu = *(const float4*)(u + (size_t)node*128 + lane*4);
    float4 acc = make_float4(uu.x + bb.x, uu.y + bb.y, uu.z + bb.z, uu.w + bb.w);

    int i = b;
    for (; i + 4 <= e; i += 4) {
        int   s0 = g_src_sorted[i],   s1 = g_src_sorted[i+1];
        int   s2 = g_src_sorted[i+2], s3 = g_src_sorted[i+3];
        float w0 = g_w_sorted[i],     w1 = g_w_sorted[i+1];
        float w2 = g_w_sorted[i+2],   w3 = g_w_sorted[i+3];
        uint2 r0 = *(const uint2*)(m + (size_t)s0*128 + lane*4);
        uint2 r1 = *(const uint2*)(m + (size_t)s1*128 + lane*4);
        uint2 r2 = *(const uint2*)(m + (size_t)s2*128 + lane*4);
        uint2 r3 = *(const uint2*)(m + (size_t)s3*128 + lane*4);
        float2 a0 = __half22float2(*(__half2*)&r0.x), b0 = __half22float2(*(__half2*)&r0.y);
        float2 a1 = __half22float2(*(__half2*)&r1.x), b1 = __half22float2(*(__half2*)&r1.y);
        float2 a2 = __half22float2(*(__half2*)&r2.x), b2 = __half22float2(*(__half2*)&r2.y);
        float2 a3 = __half22float2(*(__half2*)&r3.x), b3 = __half22float2(*(__half2*)&r3.y);
        acc.x = fmaf(w0, a0.x, fmaf(w1, a1.x, fmaf(w2, a2.x, fmaf(w3, a3.x, acc.x))));
        acc.y = fmaf(w0, a0.y, fmaf(w1, a1.y, fmaf(w2, a2.y, fmaf(w3, a3.y, acc.y))));
        acc.z = fmaf(w0, b0.x, fmaf(w1, b1.x, fmaf(w2, b2.x, fmaf(w3, b3.x, acc.z))));
        acc.w = fmaf(w0, b0.y, fmaf(w1, b1.y, fmaf(w2, b2.y, fmaf(w3, b3.y, acc.w))));
    }
    for (; i < e; i++) {
        int   s = g_src_sorted[i];
        float w = g_w_sorted[i];
        uint2 r = *(const uint2*)(m + (size_t)s*128 + lane*4);
        float2 a = __half22float2(*(__half2*)&r.x), b2 = __half22float2(*(__half2*)&r.y);
        acc.x = fmaf(w, a.x, acc.x);
        acc.y = fmaf(w, a.y, acc.y);
        acc.z = fmaf(w, b2.x, acc.z);
        acc.w = fmaf(w, b2.y, acc.w);
    }
    acc.x = tanhf(acc.x); acc.y = tanhf(acc.y);
    acc.z = tanhf(acc.z); acc.w = tanhf(acc.w);
    *(float4*)(h + (size_t)node*128 + lane*4) = acc;
}

// ================= WMMA output GEMM: out = h @ Wout.T + bout (C=32) =================
#define OLDP 136
#define OA_H 0
#define OA_L (128*OLDP*2)
#define OW_H (2*128*OLDP*2)
#define OW_L (OW_H + 32*OLDP*2)
#define OBIAS (OW_L + 32*OLDP*2)
#define OUT_SMEM (OBIAS + 16*40*4)

__global__ __launch_bounds__(256, 1) void out_gemm_wmma(
    const float* __restrict__ h, const float* __restrict__ Wout,
    const float* __restrict__ bout, float* __restrict__ out,
    float* __restrict__ scratch, int N)
{
    extern __shared__ char sm[];
    __nv_bfloat16* aH = (__nv_bfloat16*)(sm + OA_H);
    __nv_bfloat16* aL = (__nv_bfloat16*)(sm + OA_L);
    __nv_bfloat16* wH = (__nv_bfloat16*)(sm + OW_H);
    __nv_bfloat16* wL = (__nv_bfloat16*)(sm + OW_L);
    float* bs = (float*)(sm + OBIAS);
    int tid = threadIdx.x, warp = tid >> 5, lane = tid & 31;

    for (int i = tid; i < 32 * 16; i += 256) {
        int r = i >> 4, ch = i & 15;
        float4 a = *(const float4*)(Wout + r * 128 + ch * 8);
        float4 b = *(const float4*)(Wout + r * 128 + ch * 8 + 4);
        float v[8] = {a.x, a.y, a.z, a.w, b.x, b.y, b.z, b.w};
        union { unsigned short u[8]; uint4 q; } H, L;
        #pragma unroll
        for (int j = 0; j < 8; j++) {
            __nv_bfloat16 hv = __float2bfloat16(v[j]);
            __nv_bfloat16 lv = __float2bfloat16(v[j] - __bfloat162float(hv));
            H.u[j] = __bfloat16_as_ushort(hv);
            L.u[j] = __bfloat16_as_ushort(lv);
        }
        *(uint4*)(wH + r * OLDP + ch * 8) = H.q;
        *(uint4*)(wL + r * OLDP + ch * 8) = L.q;
    }
    for (int i = tid; i < 16 * 40; i += 256) {
        int c = i % 40;
        bs[i] = (c < 32) ? bout[c] : 0.f;
    }

    int ntiles = (N + 127) >> 7;
    for (int tile = blockIdx.x; tile < ntiles; tile += gridDim.x) {
        int row0 = tile << 7;
        __syncthreads();
        for (int ch = tid; ch < 2048; ch += 256) {
            int r  = ch >> 4;
            int c0 = (ch & 15) << 3;
            float v[8];
            int gr = row0 + r;
            if (gr < N) {
                float4 a = *(const float4*)(h + (size_t)gr * 128 + c0);
                float4 b = *(const float4*)(h + (size_t)gr * 128 + c0 + 4);
                v[0]=a.x; v[1]=a.y; v[2]=a.z; v[3]=a.w; v[4]=b.x; v[5]=b.y; v[6]=b.z; v[7]=b.w;
            } else {
                #pragma unroll
                for (int j = 0; j < 8; j++) v[j] = 0.f;
            }
            union { unsigned short u[8]; uint4 q; } H, L;
            #pragma unroll
            for (int j = 0; j < 8; j++) {
                __nv_bfloat16 hv = __float2bfloat16(v[j]);
                __nv_bfloat16 lv = __float2bfloat16(v[j] - __bfloat162float(hv));
                H.u[j] = __bfloat16_as_ushort(hv);
                L.u[j] = __bfloat16_as_ushort(lv);
            }
            *(uint4*)(aH + r * OLDP + c0) = H.q;
            *(uint4*)(aL + r * OLDP + c0) = L.q;
        }
        __syncthreads();

        wmma::fragment<wmma::accumulator, 16, 16, 16, float> acc[2];
        #pragma unroll
        for (int f = 0; f < 2; f++)
            wmma::load_matrix_sync(acc[f], bs + f * 16, 40, wmma::mem_row_major);

        #pragma unroll
        for (int pass = 0; pass < 3; pass++) {
            const __nv_bfloat16* A = (pass == 2) ? aL : aH;
            const __nv_bfloat16* B = (pass == 1) ? wL : wH;
            #pragma unroll
            for (int k = 0; k < 8; k++) {
                wmma::fragment<wmma::matrix_a, 16, 16, 16, __nv_bfloat16, wmma::row_major> af;
                wmma::load_matrix_sync(af, A + (warp * 16) * OLDP + k * 16, OLDP);
                #pragma unroll
                for (int f = 0; f < 2; f++) {
                    wmma::fragment<wmma::matrix_b, 16, 16, 16, __nv_bfloat16, wmma::col_major> bf;
                    wmma::load_matrix_sync(bf, B + (f * 16) * OLDP + k * 16, OLDP);
                    wmma::mma_sync(acc[f], af, bf, acc[f]);
                }
            }
        }
        int gr0 = row0 + warp * 16;
        if (gr0 + 16 <= N) {
            wmma::store_matrix_sync(out + (size_t)gr0 * 32,      acc[0], 32, wmma::mem_row_major);
            wmma::store_matrix_sync(out + (size_t)gr0 * 32 + 16, acc[1], 32, wmma::mem_row_major);
        } else if (gr0 < N) {
            float* sc = scratch + (size_t)gr0 * 32;
            wmma::store_matrix_sync(sc,      acc[0], 32, wmma::mem_row_major);
            wmma::store_matrix_sync(sc + 16, acc[1], 32, wmma::mem_row_major);
            __syncwarp();
            for (int r = 0; r < 16; r++) {
                int gr = gr0 + r;
                if (gr < N) out[(size_t)gr * 32 + lane] = sc[r * 32 + lane];
            }
        }
    }
}

extern "C" void kernel_launch(void* const* d_in, const int* in_sizes, int n_in,
                              void* d_out, int out_size) {
    const float* x    = (const float*)d_in[0];
    const void*  ei   = d_in[1];
    const float* ew   = (const float*)d_in[2];
    const float* Wm0  = (const float*)d_in[3];
    const float* Wu0  = (const float*)d_in[4];
    const float* bu0  = (const float*)d_in[5];
    const float* Wm1  = (const float*)d_in[6];
    const float* Wu1  = (const float*)d_in[7];
    const float* bu1  = (const float*)d_in[8];
    const float* Wm2  = (const float*)d_in[9];
    const float* Wu2  = (const float*)d_in[10];
    const float* bu2  = (const float*)d_in[11];
    const float* Wout = (const float*)d_in[12];
    const float* bout = (const float*)d_in[13];
    float* out = (float*)d_out;

    int N = in_sizes[0] / 128;
    int E = in_sizes[2];

    __nv_bfloat16* pW;
    __half* pm;
    float *pu, *ph, *psc;
    cudaGetSymbolAddress((void**)&pW,  g_Wbf);
    cudaGetSymbolAddress((void**)&pm,  g_m);
    cudaGetSymbolAddress((void**)&pu,  g_u);
    cudaGetSymbolAddress((void**)&ph,  g_h);
    cudaGetSymbolAddress((void**)&psc, g_scr);

    static cudaStream_t s2 = nullptr;
    static cudaEvent_t evF = nullptr, evCSR = nullptr;
    if (!s2) {
        cudaStreamCreateWithFlags(&s2, cudaStreamNonBlocking);
        cudaEventCreateWithFlags(&evF,   cudaEventDisableTiming);
        cudaEventCreateWithFlags(&evCSR, cudaEventDisableTiming);
    }

    static bool attrs_set = false;
    if (!attrs_set) {
        cudaFuncSetAttribute(dual_gemm_wmma, cudaFuncAttributeMaxDynamicSharedMemorySize, GEMM_SMEM);
        cudaFuncSetAttribute(out_gemm_wmma,  cudaFuncAttributeMaxDynamicSharedMemorySize, OUT_SMEM);
        attrs_set = true;
    }

    int eb = (E + 255) / 256;
    int ab = (N * 32 + 255) / 256;

    // fork: CSR build on s2, concurrent with prep + gemm0
    cudaEventRecord(evF, 0);
    cudaStreamWaitEvent(s2, evF, 0);
    zero_kernel<<<148, 256, 0, s2>>>(ei, N);
    hist_kernel<<<eb, 256, 0, s2>>>(ei, E);
    scan_kernel<<<1, 1024, 0, s2>>>(N);
    scatter_kernel<<<eb, 256, 0, s2>>>(ei, ew, E);
    cudaEventRecord(evCSR, s2);

    prep_kernel<<<148, 256>>>(Wm0, Wu0, Wm1, Wu1, Wm2, Wu2);

    const float* bus[3] = {bu0, bu1, bu2};
    const float* cur = x;
    for (int l = 0; l < 3; l++) {
        const __nv_bfloat16* Whi = pW + (size_t)l * 2 * 256 * 128;
        const __nv_bfloat16* Wlo = Whi + 256 * 128;
        dual_gemm_wmma<<<148, 256, GEMM_SMEM>>>(cur, Whi, Wlo, pm, pu, N);
        if (l == 0) cudaStreamWaitEvent(0, evCSR, 0);   // join CSR before first aggregate
        float* hbuf = ph + (size_t)(l & 1) * NMAX * 128;
        agg_tanh<<<ab, 256>>>(pm, pu, bus[l], hbuf, N);
        cur = hbuf;
    }
    out_gemm_wmma<<<148, 256, OUT_SMEM>>>(cur, Wout, bout, out, psc, N);
    (void)n_in; (void)out_size;
}

// round 11
// speedup vs baseline: 1.3397x; 1.0002x over previous
#include <cuda_runtime.h>
#include <cuda_bf16.h>
#include <cuda_fp16.h>
#include <mma.h>
#include <stdint.h>
#include <math.h>

using namespace nvcuda;

#define NMAX 50048   // 391 * 128, WMMA tile stores never OOB
#define EMAX 1000000

__device__ __nv_bfloat16 g_Wbf[3][2][256*128]; // [layer][hi/lo][c][k]
__device__ __half g_m[NMAX*128];               // fp16 messages
__device__ float  g_u[NMAX*128];
__device__ __nv_bfloat16 g_hH[NMAX*128];       // h (or x) hi part
__device__ __nv_bfloat16 g_hL[NMAX*128];       // h (or x) lo part
__device__ float  g_scr[NMAX*32];
__device__ int    g_is64;
__device__ int    g_cnt[NMAX];
__device__ int    g_off[NMAX + 1];
__device__ int    g_cur[NMAX];
__device__ int    g_src_sorted[EMAX];
__device__ float  g_w_sorted[EMAX];

// ================= prep: weights + x -> bf16 hi/lo =================
__global__ void prep_kernel(const float* __restrict__ Wm0, const float* __restrict__ Wu0,
                            const float* __restrict__ Wm1, const float* __restrict__ Wu1,
                            const float* __restrict__ Wm2, const float* __restrict__ Wu2,
                            const float* __restrict__ x, int N) {
    int idx = blockIdx.x * blockDim.x + threadIdx.x;
    const int wt = 3 * 256 * 128;
    for (int t = idx; t < wt; t += gridDim.x * blockDim.x) {
        int l = t / (256 * 128);
        int r = t % (256 * 128);
        int c = r / 128;
        int k = r % 128;
        const float* W;
        if (c < 128) W = (l == 0) ? Wm0 : (l == 1) ? Wm1 : Wm2;
        else         W = (l == 0) ? Wu0 : (l == 1) ? Wu1 : Wu2;
        float v = W[(c & 127) * 128 + k];
        __nv_bfloat16 hi = __float2bfloat16(v);
        __nv_bfloat16 lo = __float2bfloat16(v - __bfloat162float(hi));
        g_Wbf[l][0][c * 128 + k] = hi;
        g_Wbf[l][1][c * 128 + k] = lo;
    }
    int xt = N * 128 / 4;
    for (int t = idx; t < xt; t += gridDim.x * blockDim.x) {
        float4 v = ((const float4*)x)[t];
        union { unsigned short u[4]; uint2 q; } H, L;
        float vv[4] = {v.x, v.y, v.z, v.w};
        #pragma unroll
        for (int j = 0; j < 4; j++) {
            __nv_bfloat16 hv = __float2bfloat16(vv[j]);
            __nv_bfloat16 lv = __float2bfloat16(vv[j] - __bfloat162float(hv));
            H.u[j] = __bfloat16_as_ushort(hv);
            L.u[j] = __bfloat16_as_ushort(lv);
        }
        ((uint2*)g_hH)[t] = H.q;
        ((uint2*)g_hL)[t] = L.q;
    }
}

// ================= CSR build (forked stream) =================
__global__ void zero_kernel(const void* __restrict__ ei, int N) {
    int idx = blockIdx.x * blockDim.x + threadIdx.x;
    if (idx == 0) {
        const int* p = (const int*)ei;
        int is64 = 1;
        for (int i = 0; i < 32; i++) if (p[2*i + 1] != 0) { is64 = 0; break; }
        g_is64 = is64;
    }
    for (int t = idx; t < N; t += gridDim.x * blockDim.x) g_cnt[t] = 0;
}

__global__ void hist_kernel(const void* __restrict__ ei, int E) {
    int i = blockIdx.x * blockDim.x + threadIdx.x;
    if (i >= E) return;
    int dst = g_is64 ? (int)((const long long*)ei)[E + i] : ((const int*)ei)[E + i];
    atomicAdd(&g_cnt[dst], 1);
}

__global__ __launch_bounds__(1024) void scan_kernel(int N) {
    __shared__ int part[1024];
    int t = threadIdx.x;
    int chunk = (N + 1023) / 1024;
    int b = t * chunk;
    int e = min(b + chunk, N);
    int s = 0;
    for (int i = b; i < e; i++) s += g_cnt[i];
    part[t] = s;
    __syncthreads();
    for (int d = 1; d < 1024; d <<= 1) {
        int v = (t >= d) ? part[t - d] : 0;
        __syncthreads();
        part[t] += v;
        __syncthreads();
    }
    int run = (t == 0) ? 0 : part[t - 1];
    for (int i = b; i < e; i++) {
        int c = g_cnt[i];
        g_off[i] = run;
        g_cur[i] = run;
        run += c;
    }
    if (e == N && b <= N) g_off[N] = run;
}

__global__ void scatter_kernel(const void* __restrict__ ei, const float* __restrict__ ew, int E) {
    int i = blockIdx.x * blockDim.x + threadIdx.x;
    if (i >= E) return;
    int src, dst;
    if (g_is64) {
        const long long* p = (const long long*)ei;
        src = (int)p[i]; dst = (int)p[E + i];
    } else {
        const int* p = (const int*)ei;
        src = p[i]; dst = p[E + i];
    }
    int pos = atomicAdd(&g_cur[dst], 1);
    g_src_sorted[pos] = src;
    g_w_sorted[pos]   = ew[i];
}

// ================= WMMA dual GEMM: A pre-split bf16 hi/lo =================
#define LDP 136
#define XS_H 0
#define XS_L (128*LDP*2)
#define WS_H (2*128*LDP*2)
#define WS_L (WS_H + 256*LDP*2)
#define G_EPI (WS_L + 256*LDP*2)
#define GEMM_SMEM (G_EPI + 8*256*4)

__global__ __launch_bounds__(256, 1) void dual_gemm_wmma(
    const __nv_bfloat16* __restrict__ aHg, const __nv_bfloat16* __restrict__ aLg,
    const __nv_bfloat16* __restrict__ Whi, const __nv_bfloat16* __restrict__ Wlo,
    __half* __restrict__ outm, float* __restrict__ outu, int N)
{
    extern __shared__ char sm[];
    __nv_bfloat16* xsH = (__nv_bfloat16*)(sm + XS_H);
    __nv_bfloat16* xsL = (__nv_bfloat16*)(sm + XS_L);
    __nv_bfloat16* wsH = (__nv_bfloat16*)(sm + WS_H);
    __nv_bfloat16* wsL = (__nv_bfloat16*)(sm + WS_L);
    int tid = threadIdx.x, warp = tid >> 5, lane = tid & 31;
    float* ep = (float*)(sm + G_EPI) + warp * 256;

    for (int i = tid; i < 256 * 16; i += 256) {
        int r = i >> 4, ch = i & 15;
        ((uint4*)(wsH + r * LDP))[ch] = ((const uint4*)(Whi + r * 128))[ch];
        ((uint4*)(wsL + r * LDP))[ch] = ((const uint4*)(Wlo + r * 128))[ch];
    }

    int ntiles = (N + 127) >> 7;

    for (int tile = blockIdx.x; tile < ntiles; tile += gridDim.x) {
        int row0 = tile << 7;
        __syncthreads();
        // pure copy staging (no conversion): 128 rows x 16 uint4 per buffer
        for (int i = tid; i < 2048; i += 256) {
            int r = i >> 4, ch = i & 15;
            size_t g = (size_t)(row0 + r) * 128;   // row0+127 < NMAX always
            ((uint4*)(xsH + r * LDP))[ch] = ((const uint4*)(aHg + g))[ch];
            ((uint4*)(xsL + r * LDP))[ch] = ((const uint4*)(aLg + g))[ch];
        }
        __syncthreads();

        int gr0 = row0 + warp * 16;
        #pragma unroll
        for (int nc = 0; nc < 4; nc++) {
            wmma::fragment<wmma::accumulator, 16, 16, 16, float> acc[4];
            #pragma unroll
            for (int f = 0; f < 4; f++) wmma::fill_fragment(acc[f], 0.0f);

            #pragma unroll
            for (int pass = 0; pass < 3; pass++) {
                const __nv_bfloat16* A = (pass == 2) ? xsL : xsH;
                const __nv_bfloat16* B = (pass == 1) ? wsL : wsH;
                #pragma unroll
                for (int k = 0; k < 8; k++) {
                    wmma::fragment<wmma::matrix_a, 16, 16, 16, __nv_bfloat16, wmma::row_major> af;
                    wmma::load_matrix_sync(af, A + (warp * 16) * LDP + k * 16, LDP);
                    #pragma unroll
                    for (int f = 0; f < 4; f++) {
                        wmma::fragment<wmma::matrix_b, 16, 16, 16, __nv_bfloat16, wmma::col_major> bf;
                        wmma::load_matrix_sync(bf, B + (nc * 64 + f * 16) * LDP + k * 16, LDP);
                        wmma::mma_sync(acc[f], af, bf, acc[f]);
                    }
                }
            }
            #pragma unroll
            for (int f = 0; f < 4; f++) {
                int n0 = nc * 64 + f * 16;
                if (n0 < 128) {
                    wmma::store_matrix_sync(ep, acc[f], 16, wmma::mem_row_major);
                    __syncwarp();
                    int row = lane >> 1, c0 = (lane & 1) * 8;
                    const float* s = ep + row * 16 + c0;
                    union { __half h[8]; uint4 q; } o;
                    #pragma unroll
                    for (int j = 0; j < 8; j++) o.h[j] = __float2half_rn(s[j]);
                    *(uint4*)(outm + (size_t)(gr0 + row) * 128 + n0 + c0) = o.q;
                    __syncwarp();
                } else {
                    wmma::store_matrix_sync(outu + (size_t)gr0 * 128 + (n0 - 128),
                                            acc[f], 128, wmma::mem_row_major);
                }
            }
        }
    }
}

// ================= fused CSR aggregate (fp16 gather) + bias + tanh -> bf16 hi/lo =================
__global__ __launch_bounds__(256) void agg_tanh(
    const __half* __restrict__ m, const float* __restrict__ u,
    const float* __restrict__ bu,
    __nv_bfloat16* __restrict__ hH, __nv_bfloat16* __restrict__ hL, int N)
{
    int node = (blockIdx.x * blockDim.x + threadIdx.x) >> 5;
    int lane = threadIdx.x & 31;
    if (node >= N) return;
    int b = g_off[node], e = g_off[node + 1];

    float4 bb = *(const float4*)(bu + lane*4);
    float4 uu = *(const float4*)(u + (size_t)node*128 + lane*4);
    float4 acc = make_float4(uu.x + bb.x, uu.y + bb.y, uu.z + bb.z, uu.w + bb.w);

    int i = b;
    for (; i + 4 <= e; i += 4) {
        int   s0 = g_src_sorted[i],   s1 = g_src_sorted[i+1];
        int   s2 = g_src_sorted[i+2], s3 = g_src_sorted[i+3];
        float w0 = g_w_sorted[i],     w1 = g_w_sorted[i+1];
        float w2 = g_w_sorted[i+2],   w3 = g_w_sorted[i+3];
        uint2 r0 = *(const uint2*)(m + (size_t)s0*128 + lane*4);
        uint2 r1 = *(const uint2*)(m + (size_t)s1*128 + lane*4);
        uint2 r2 = *(const uint2*)(m + (size_t)s2*128 + lane*4);
        uint2 r3 = *(const uint2*)(m + (size_t)s3*128 + lane*4);
        float2 a0 = __half22float2(*(__half2*)&r0.x), b0 = __half22float2(*(__half2*)&r0.y);
        float2 a1 = __half22float2(*(__half2*)&r1.x), b1 = __half22float2(*(__half2*)&r1.y);
        float2 a2 = __half22float2(*(__half2*)&r2.x), b2 = __half22float2(*(__half2*)&r2.y);
        float2 a3 = __half22float2(*(__half2*)&r3.x), b3 = __half22float2(*(__half2*)&r3.y);
        acc.x = fmaf(w0, a0.x, fmaf(w1, a1.x, fmaf(w2, a2.x, fmaf(w3, a3.x, acc.x))));
        acc.y = fmaf(w0, a0.y, fmaf(w1, a1.y, fmaf(w2, a2.y, fmaf(w3, a3.y, acc.y))));
        acc.z = fmaf(w0, b0.x, fmaf(w1, b1.x, fmaf(w2, b2.x, fmaf(w3, b3.x, acc.z))));
        acc.w = fmaf(w0, b0.y, fmaf(w1, b1.y, fmaf(w2, b2.y, fmaf(w3, b3.y, acc.w))));
    }
    for (; i < e; i++) {
        int   s = g_src_sorted[i];
        float w = g_w_sorted[i];
        uint2 r = *(const uint2*)(m + (size_t)s*128 + lane*4);
        float2 a = __half22float2(*(__half2*)&r.x), b2 = __half22float2(*(__half2*)&r.y);
        acc.x = fmaf(w, a.x, acc.x);
        acc.y = fmaf(w, a.y, acc.y);
        acc.z = fmaf(w, b2.x, acc.z);
        acc.w = fmaf(w, b2.y, acc.w);
    }
    float v[4] = {tanhf(acc.x), tanhf(acc.y), tanhf(acc.z), tanhf(acc.w)};
    union { unsigned short us[4]; uint2 q; } H, L;
    #pragma unroll
    for (int j = 0; j < 4; j++) {
        __nv_bfloat16 hv = __float2bfloat16(v[j]);
        __nv_bfloat16 lv = __float2bfloat16(v[j] - __bfloat162float(hv));
        H.us[j] = __bfloat16_as_ushort(hv);
        L.us[j] = __bfloat16_as_ushort(lv);
    }
    *(uint2*)(hH + (size_t)node*128 + lane*4) = H.q;
    *(uint2*)(hL + (size_t)node*128 + lane*4) = L.q;
}

// ================= WMMA output GEMM: out = h @ Wout.T + bout (C=32) =================
#define OLDP 136
#define OA_H 0
#define OA_L (128*OLDP*2)
#define OW_H (2*128*OLDP*2)
#define OW_L (OW_H + 32*OLDP*2)
#define OBIAS (OW_L + 32*OLDP*2)
#define OUT_SMEM (OBIAS + 16*40*4)

__global__ __launch_bounds__(256, 1) void out_gemm_wmma(
    const __nv_bfloat16* __restrict__ aHg, const __nv_bfloat16* __restrict__ aLg,
    const float* __restrict__ Wout,
    const float* __restrict__ bout, float* __restrict__ out,
    float* __restrict__ scratch, int N)
{
    extern __shared__ char sm[];
    __nv_bfloat16* aH = (__nv_bfloat16*)(sm + OA_H);
    __nv_bfloat16* aL = (__nv_bfloat16*)(sm + OA_L);
    __nv_bfloat16* wH = (__nv_bfloat16*)(sm + OW_H);
    __nv_bfloat16* wL = (__nv_bfloat16*)(sm + OW_L);
    float* bs = (float*)(sm + OBIAS);
    int tid = threadIdx.x, warp = tid >> 5, lane = tid & 31;

    for (int i = tid; i < 32 * 16; i += 256) {
        int r = i >> 4, ch = i & 15;
        float4 a = *(const float4*)(Wout + r * 128 + ch * 8);
        float4 b = *(const float4*)(Wout + r * 128 + ch * 8 + 4);
        float v[8] = {a.x, a.y, a.z, a.w, b.x, b.y, b.z, b.w};
        union { unsigned short u[8]; uint4 q; } H, L;
        #pragma unroll
        for (int j = 0; j < 8; j++) {
            __nv_bfloat16 hv = __float2bfloat16(v[j]);
            __nv_bfloat16 lv = __float2bfloat16(v[j] - __bfloat162float(hv));
            H.u[j] = __bfloat16_as_ushort(hv);
            L.u[j] = __bfloat16_as_ushort(lv);
        }
        *(uint4*)(wH + r * OLDP + ch * 8) = H.q;
        *(uint4*)(wL + r * OLDP + ch * 8) = L.q;
    }
    for (int i = tid; i < 16 * 40; i += 256) {
        int c = i % 40;
        bs[i] = (c < 32) ? bout[c] : 0.f;
    }

    int ntiles = (N + 127) >> 7;
    for (int tile = blockIdx.x; tile < ntiles; tile += gridDim.x) {
        int row0 = tile << 7;
        __syncthreads();
        for (int i = tid; i < 2048; i += 256) {
            int r = i >> 4, ch = i & 15;
            size_t g = (size_t)(row0 + r) * 128;
            ((uint4*)(aH + r * OLDP))[ch] = ((const uint4*)(aHg + g))[ch];
            ((uint4*)(aL + r * OLDP))[ch] = ((const uint4*)(aLg + g))[ch];
        }
        __syncthreads();

        wmma::fragment<wmma::accumulator, 16, 16, 16, float> acc[2];
        #pragma unroll
        for (int f = 0; f < 2; f++)
            wmma::load_matrix_sync(acc[f], bs + f * 16, 40, wmma::mem_row_major);

        #pragma unroll
        for (int pass = 0; pass < 3; pass++) {
            const __nv_bfloat16* A = (pass == 2) ? aL : aH;
            const __nv_bfloat16* B = (pass == 1) ? wL : wH;
            #pragma unroll
            for (int k = 0; k < 8; k++) {
                wmma::fragment<wmma::matrix_a, 16, 16, 16, __nv_bfloat16, wmma::row_major> af;
                wmma::load_matrix_sync(af, A + (warp * 16) * OLDP + k * 16, OLDP);
                #pragma unroll
                for (int f = 0; f < 2; f++) {
                    wmma::fragment<wmma::matrix_b, 16, 16, 16, __nv_bfloat16, wmma::col_major> bf;
                    wmma::load_matrix_sync(bf, B + (f * 16) * OLDP + k * 16, OLDP);
                    wmma::mma_sync(acc[f], af, bf, acc[f]);
                }
            }
        }
        int gr0 = row0 + warp * 16;
        if (gr0 + 16 <= N) {
            wmma::store_matrix_sync(out + (size_t)gr0 * 32,      acc[0], 32, wmma::mem_row_major);
            wmma::store_matrix_sync(out + (size_t)gr0 * 32 + 16, acc[1], 32, wmma::mem_row_major);
        } else if (gr0 < N) {
            float* sc = scratch + (size_t)gr0 * 32;
            wmma::store_matrix_sync(sc,      acc[0], 32, wmma::mem_row_major);
            wmma::store_matrix_sync(sc + 16, acc[1], 32, wmma::mem_row_major);
            __syncwarp();
            for (int r = 0; r < 16; r++) {
                int gr = gr0 + r;
                if (gr < N) out[(size_t)gr * 32 + lane] = sc[r * 32 + lane];
            }
        }
    }
}

extern "C" void kernel_launch(void* const* d_in, const int* in_sizes, int n_in,
                              void* d_out, int out_size) {
    const float* x    = (const float*)d_in[0];
    const void*  ei   = d_in[1];
    const float* ew   = (const float*)d_in[2];
    const float* Wm0  = (const float*)d_in[3];
    const float* Wu0  = (const float*)d_in[4];
    const float* bu0  = (const float*)d_in[5];
    const float* Wm1  = (const float*)d_in[6];
    const float* Wu1  = (const float*)d_in[7];
    const float* bu1  = (const float*)d_in[8];
    const float* Wm2  = (const float*)d_in[9];
    const float* Wu2  = (const float*)d_in[10];
    const float* bu2  = (const float*)d_in[11];
    const float* Wout = (const float*)d_in[12];
    const float* bout = (const float*)d_in[13];
    float* out = (float*)d_out;

    int N = in_sizes[0] / 128;
    int E = in_sizes[2];

    __nv_bfloat16 *pW, *phH, *phL;
    __half* pm;
    float *pu, *psc;
    cudaGetSymbolAddress((void**)&pW,  g_Wbf);
    cudaGetSymbolAddress((void**)&pm,  g_m);
    cudaGetSymbolAddress((void**)&pu,  g_u);
    cudaGetSymbolAddress((void**)&phH, g_hH);
    cudaGetSymbolAddress((void**)&phL, g_hL);
    cudaGetSymbolAddress((void**)&psc, g_scr);

    static cudaStream_t s2 = nullptr;
    static cudaEvent_t evF = nullptr, evCSR = nullptr;
    if (!s2) {
        cudaStreamCreateWithFlags(&s2, cudaStreamNonBlocking);
        cudaEventCreateWithFlags(&evF,   cudaEventDisableTiming);
        cudaEventCreateWithFlags(&evCSR, cudaEventDisableTiming);
    }

    static bool attrs_set = false;
    if (!attrs_set) {
        cudaFuncSetAttribute(dual_gemm_wmma, cudaFuncAttributeMaxDynamicSharedMemorySize, GEMM_SMEM);
        cudaFuncSetAttribute(out_gemm_wmma,  cudaFuncAttributeMaxDynamicSharedMemorySize, OUT_SMEM);
        attrs_set = true;
    }

    int eb = (E + 255) / 256;
    int ab = (N * 32 + 255) / 256;

    // fork: CSR build on s2, concurrent with prep + gemm0
    cudaEventRecord(evF, 0);
    cudaStreamWaitEvent(s2, evF, 0);
    zero_kernel<<<148, 256, 0, s2>>>(ei, N);
    hist_kernel<<<eb, 256, 0, s2>>>(ei, E);
    scan_kernel<<<1, 1024, 0, s2>>>(N);
    scatter_kernel<<<eb, 256, 0, s2>>>(ei, ew, E);
    cudaEventRecord(evCSR, s2);

    prep_kernel<<<148, 256>>>(Wm0, Wu0, Wm1, Wu1, Wm2, Wu2, x, N);

    const float* bus[3] = {bu0, bu1, bu2};
    for (int l = 0; l < 3; l++) {
        const __nv_bfloat16* Whi = pW + (size_t)l * 2 * 256 * 128;
        const __nv_bfloat16* Wlo = Whi + 256 * 128;
        dual_gemm_wmma<<<148, 256, GEMM_SMEM>>>(phH, phL, Whi, Wlo, pm, pu, N);
        if (l == 0) cudaStreamWaitEvent(0, evCSR, 0);   // join CSR before first aggregate
        agg_tanh<<<ab, 256>>>(pm, pu, bus[l], phH, phL, N);
    }
    out_gemm_wmma<<<148, 256, OUT_SMEM>>>(phH, phL, Wout, bout, out, psc, N);
    (void)n_in; (void)out_size;
}